// round 6
// baseline (speedup 1.0000x reference)
#include <cuda_runtime.h>
#include <cstdint>
#include <math.h>

// Problem constants
#define NBINS (1 << 21)          // 128^3
#define NPIX  (4096 * 4096)      // 16,777,216 pixels
#define NFLAGW (NBINS / 32)      // 65536 flag words
#define NGRP   (NPIX / 4)        // 4-pixel groups

// Fixed-point mask accumulation: 24 fractional bits, count in bits [40:64)
#define MASK_SCALE 16777216.0f        // 2^24
#define MASK_INV_SCALE (1.0f / 16777216.0f)
#define MASK_INV_SCALE_D (1.0 / 16777216.0)
#define COUNT_SHIFT 40
#define MASK40 0xFFFFFFFFFFULL        // low 40 bits
#define BIN21 0x1FFFFFULL

// k_out smem bit-table coverage: 57344 words * 32 bins = 1,835,008 bins (224 KB)
#define SMEM_WORDS 57344
#define SMEM_BYTES (SMEM_WORDS * 4)

// Scratch (allocation-free rule: __device__ globals)
__device__ unsigned long long g_hist[NBINS];   // 16 MB, packed count|mask
__device__ float              g_logr[NBINS];   // 8 MB
__device__ unsigned long long g_b64[NGRP];     // 32 MB: bins 0..2 of each 4-px group
__device__ unsigned int       g_b32[NGRP];     // 16 MB: bin 3 of each group
__device__ unsigned int       g_flag[NFLAGW];  // 256 KB bit table
__device__ double             g_sumf_in, g_suml_in, g_avg;
__device__ unsigned long long g_mask_total;

// ---------------------------------------------------------------------------
// K0: clear histogram (vectorized) + scalars
// ---------------------------------------------------------------------------
__global__ void k_clear() {
    int i = blockIdx.x * blockDim.x + threadIdx.x;
    if (i < NBINS / 2) ((ulonglong2*)g_hist)[i] = make_ulonglong2(0ULL, 0ULL);
    if (i == 0) {
        g_sumf_in = 0.0; g_suml_in = 0.0; g_avg = 0.0;
        g_mask_total = 0ULL;
    }
}

// ---------------------------------------------------------------------------
// K1: histogram accumulate + packed bin store. 8 pixels per thread,
// all loads front-batched for MLP. Numerics identical to R5.
// ---------------------------------------------------------------------------
__global__ void __launch_bounds__(256) k_hist(const int* __restrict__ img,
                                              const float* __restrict__ mask) {
    int t = blockIdx.x * blockDim.x + threadIdx.x;   // 0 .. NPIX/8-1
    if (t >= NPIX / 8) return;

    const int4*   img4  = (const int4*)img;
    const float4* mask4 = (const float4*)mask;

    int4 c0 = img4[t * 6 + 0];
    int4 c1 = img4[t * 6 + 1];
    int4 c2 = img4[t * 6 + 2];
    int4 c3 = img4[t * 6 + 3];
    int4 c4 = img4[t * 6 + 4];
    int4 c5 = img4[t * 6 + 5];
    float4 m0 = mask4[t * 2 + 0];
    float4 m1 = mask4[t * 2 + 1];

    int v[24] = {c0.x,c0.y,c0.z,c0.w, c1.x,c1.y,c1.z,c1.w, c2.x,c2.y,c2.z,c2.w,
                 c3.x,c3.y,c3.z,c3.w, c4.x,c4.y,c4.z,c4.w, c5.x,c5.y,c5.z,c5.w};
    float mm[8] = {m0.x,m0.y,m0.z,m0.w, m1.x,m1.y,m1.z,m1.w};

    int bins[8];
    #pragma unroll
    for (int j = 0; j < 8; j++)
        bins[j] = ((v[3*j] >> 1) << 14) | ((v[3*j+1] >> 1) << 7) | (v[3*j+2] >> 1);

    #pragma unroll
    for (int j = 0; j < 8; j++) {
        unsigned long long val = (1ULL << COUNT_SHIFT)
                               | (unsigned long long)(mm[j] * MASK_SCALE + 0.5f);
        atomicAdd(&g_hist[bins[j]], val);
    }

    // Pack: group g = 2t (pixels 0-3), group 2t+1 (pixels 4-7)
    unsigned long long w0 = (unsigned long long)bins[0]
                          | ((unsigned long long)bins[1] << 21)
                          | ((unsigned long long)bins[2] << 42);
    unsigned long long w1 = (unsigned long long)bins[4]
                          | ((unsigned long long)bins[5] << 21)
                          | ((unsigned long long)bins[6] << 42);
    ((ulonglong2*)g_b64)[t] = make_ulonglong2(w0, w1);
    ((uint2*)g_b32)[t] = make_uint2((unsigned int)bins[3], (unsigned int)bins[7]);
}

// ---------------------------------------------------------------------------
// K2: sums. Integer-exact mask total (u64), float partials for the input
// arrays (double only at the block-level atomic). Count total == NPIX exactly.
// ---------------------------------------------------------------------------
__global__ void __launch_bounds__(256) k_sums(const float* __restrict__ full_in,
                                              const float* __restrict__ lines_in) {
    int t = blockIdx.x * blockDim.x + threadIdx.x;   // 0 .. NBINS/4-1
    unsigned long long msum = 0ULL;
    float fsum = 0.0f, lsum = 0.0f;
    if (t < NBINS / 4) {
        ulonglong2 h01 = ((const ulonglong2*)g_hist)[t * 2 + 0];
        ulonglong2 h23 = ((const ulonglong2*)g_hist)[t * 2 + 1];
        msum = (h01.x & MASK40) + (h01.y & MASK40) + (h23.x & MASK40) + (h23.y & MASK40);
        float4 f4 = ((const float4*)full_in)[t];
        float4 l4 = ((const float4*)lines_in)[t];
        fsum = (f4.x + f4.y) + (f4.z + f4.w);
        lsum = (l4.x + l4.y) + (l4.z + l4.w);
    }
    for (int o = 16; o > 0; o >>= 1) {
        msum += __shfl_down_sync(0xFFFFFFFFu, msum, o);
        fsum += __shfl_down_sync(0xFFFFFFFFu, fsum, o);
        lsum += __shfl_down_sync(0xFFFFFFFFu, lsum, o);
    }
    __shared__ unsigned long long sm[8];
    __shared__ float sf[8], sl[8];
    int lane = threadIdx.x & 31, wid = threadIdx.x >> 5;
    if (lane == 0) { sm[wid] = msum; sf[wid] = fsum; sl[wid] = lsum; }
    __syncthreads();
    if (wid == 0) {
        msum = (lane < 8) ? sm[lane] : 0ULL;
        fsum = (lane < 8) ? sf[lane] : 0.0f;
        lsum = (lane < 8) ? sl[lane] : 0.0f;
        for (int o = 4; o > 0; o >>= 1) {
            msum += __shfl_down_sync(0xFFFFFFFFu, msum, o);
            fsum += __shfl_down_sync(0xFFFFFFFFu, fsum, o);
            lsum += __shfl_down_sync(0xFFFFFFFFu, lsum, o);
        }
        if (lane == 0) {
            atomicAdd(&g_mask_total, msum);
            atomicAdd(&g_sumf_in, (double)fsum);
            atomicAdd(&g_suml_in, (double)lsum);
        }
    }
}

// ---------------------------------------------------------------------------
// K3: per-bin log ratio + avg. Scalars (C, inv_sl) derived per-block from the
// device totals with the exact double expression previously in k_prep —
// deterministic, identical across blocks. lr = logf(l/f) + C.
// ---------------------------------------------------------------------------
__global__ void __launch_bounds__(256) k_logr(const float* __restrict__ full_in,
                                              const float* __restrict__ lines_in) {
    __shared__ float sC, sInvSl;
    if (threadIdx.x == 0) {
        double sfd = g_sumf_in + (double)NPIX + (double)NBINS;
        double sld = g_suml_in + (double)g_mask_total * MASK_INV_SCALE_D
                   + (double)NBINS * 1e-10;
        sC = (float)(log(sfd) - log(sld));
        sInvSl = (float)(1.0 / sld);
    }
    __syncthreads();
    float C = sC, inv_sl = sInvSl;

    int t = blockIdx.x * blockDim.x + threadIdx.x;   // 0 .. NBINS/4-1
    float avg = 0.0f;
    if (t < NBINS / 4) {
        ulonglong2 h01 = ((const ulonglong2*)g_hist)[t * 2 + 0];
        ulonglong2 h23 = ((const ulonglong2*)g_hist)[t * 2 + 1];
        float4 f4 = ((const float4*)full_in)[t];
        float4 l4 = ((const float4*)lines_in)[t];
        unsigned long long hh[4] = {h01.x, h01.y, h23.x, h23.y};
        float ff[4] = {f4.x, f4.y, f4.z, f4.w};
        float ll[4] = {l4.x, l4.y, l4.z, l4.w};
        float lrout[4];
        #pragma unroll
        for (int i = 0; i < 4; i++) {
            float cnt = (float)(hh[i] >> COUNT_SHIFT);
            float ms  = (float)(hh[i] & MASK40) * MASK_INV_SCALE;
            float f = ff[i] + cnt + 1.0f;
            float l = ll[i] + ms + 1e-10f;
            float lr = logf(l / f) + C;
            lrout[i] = lr;
            avg += (l * inv_sl) * lr;
        }
        ((float4*)g_logr)[t] = make_float4(lrout[0], lrout[1], lrout[2], lrout[3]);
    }
    for (int o = 16; o > 0; o >>= 1)
        avg += __shfl_down_sync(0xFFFFFFFFu, avg, o);
    __shared__ float sa[8];
    int lane = threadIdx.x & 31, wid = threadIdx.x >> 5;
    if (lane == 0) sa[wid] = avg;
    __syncthreads();
    if (wid == 0) {
        avg = (lane < 8) ? sa[lane] : 0.0f;
        for (int o = 4; o > 0; o >>= 1)
            avg += __shfl_down_sync(0xFFFFFFFFu, avg, o);
        if (lane == 0) atomicAdd(&g_avg, (double)avg);
    }
}

// ---------------------------------------------------------------------------
// K3b: build 1-bit flag table via ballot
// ---------------------------------------------------------------------------
__global__ void __launch_bounds__(256) k_flag() {
    int i = blockIdx.x * blockDim.x + threadIdx.x;   // 0 .. NBINS-1
    float avgf = (float)g_avg;
    unsigned int m = __ballot_sync(0xFFFFFFFFu, g_logr[i] > avgf);
    if ((i & 31) == 0) g_flag[i >> 5] = m;
}

// ---------------------------------------------------------------------------
// K4: gather, 8 px/thread from packed bins. 224KB of the bit table in smem,
// remainder via L2. Persistent: 148 blocks x 1024 threads.
// ---------------------------------------------------------------------------
__device__ __forceinline__ float flag_lookup(const unsigned int* s_flag, int bin) {
    int w = bin >> 5, bit = bin & 31;
    unsigned int word = (w < SMEM_WORDS) ? s_flag[w] : __ldg(&g_flag[w]);
    return (float)((word >> bit) & 1u);
}

__global__ void __launch_bounds__(1024) k_out(float* __restrict__ out) {
    extern __shared__ unsigned int s_flag[];
    for (int i = threadIdx.x; i < SMEM_WORDS; i += 1024)
        s_flag[i] = g_flag[i];
    __syncthreads();

    int stride = gridDim.x * 1024;
    for (int t = blockIdx.x * 1024 + threadIdx.x; t < NPIX / 8; t += stride) {
        ulonglong2 ww = ((const ulonglong2*)g_b64)[t];
        uint2 xx = ((const uint2*)g_b32)[t];
        float4 o0, o1;
        o0.x = flag_lookup(s_flag, (int)( ww.x        & BIN21));
        o0.y = flag_lookup(s_flag, (int)((ww.x >> 21) & BIN21));
        o0.z = flag_lookup(s_flag, (int)( ww.x >> 42));
        o0.w = flag_lookup(s_flag, (int)xx.x);
        o1.x = flag_lookup(s_flag, (int)( ww.y        & BIN21));
        o1.y = flag_lookup(s_flag, (int)((ww.y >> 21) & BIN21));
        o1.z = flag_lookup(s_flag, (int)( ww.y >> 42));
        o1.w = flag_lookup(s_flag, (int)xx.y);
        ((float4*)out)[t * 2 + 0] = o0;
        ((float4*)out)[t * 2 + 1] = o1;
    }
}

extern "C" void kernel_launch(void* const* d_in, const int* in_sizes, int n_in,
                              void* d_out, int out_size) {
    const int*   img      = (const int*)d_in[0];
    const float* mask     = (const float*)d_in[1];
    const float* full_in  = (const float*)d_in[2];
    const float* lines_in = (const float*)d_in[3];
    float* out            = (float*)d_out;

    // Idempotent opt-in for 224KB dynamic smem (non-stream call; capture-safe).
    cudaFuncSetAttribute(k_out, cudaFuncAttributeMaxDynamicSharedMemorySize, SMEM_BYTES);

    k_clear<<<(NBINS / 2) / 256, 256>>>();
    k_hist <<<(NPIX / 8) / 256, 256>>>(img, mask);
    k_sums <<<(NBINS / 4) / 256, 256>>>(full_in, lines_in);
    k_logr <<<(NBINS / 4) / 256, 256>>>(full_in, lines_in);
    k_flag <<<NBINS / 256, 256>>>();
    k_out  <<<148, 1024, SMEM_BYTES>>>(out);
}